// round 8
// baseline (speedup 1.0000x reference)
#include <cuda_runtime.h>
#include <cstdint>
#include <math.h>

// Problem dims
#define B_ 2
#define T_ 256
#define N_ 128
#define F_ 16
#define D_ 128
#define H_ 288
#define E_ 1024
#define M_TOTAL (B_*T_*N_)   // 65536 flattened node-time rows

// Chain kernel tiling
#define BM 128
#define LDA 132              // 128 + 4 pad
#define NTH 512
#define WCHUNK (32*LDA)
#define CHAIN_SMEM ((2*BM*LDA + 2*WCHUNK) * sizeof(float))   // 168960 B

typedef unsigned long long u64;

// Scratch (static device arrays: allocation-free per harness rules)
__device__ float g_S1[(size_t)M_TOTAL * H_];   // send @ Wc1[0:128,:]
__device__ float g_R1[(size_t)M_TOTAL * H_];   // recv @ Wc1[144:272,:]
__device__ float g_pet[255 * H_];              // pe terms + bc1

// ---------------- f32x2 helpers (Blackwell packed fp32, base sm_100) -------
__device__ __forceinline__ u64 pack_ff(float x) {
    u64 r;
    asm("mov.b64 %0, {%1, %1};" : "=l"(r) : "f"(x));
    return r;
}
__device__ __forceinline__ void fma2(u64& d, u64 a, u64 b) {
    asm("fma.rn.f32x2 %0, %1, %2, %0;" : "+l"(d) : "l"(a), "l"(b));
}
__device__ __forceinline__ float2 unpack_ff(u64 v) {
    float2 f;
    asm("mov.b64 {%0, %1}, %2;" : "=f"(f.x), "=f"(f.y) : "l"(v));
    return f;
}

// ---------------------------------------------------------------------------
// weight chunk loaders (512 threads)
// ---------------------------------------------------------------------------
__device__ __forceinline__ void load_w128(float* __restrict__ dst,
                                          const float* __restrict__ Wg,
                                          int kc, int tid)
{
    #pragma unroll
    for (int it = 0; it < 2; it++) {
        int l  = tid + it * NTH;              // 0..1023
        int kk = l >> 5;
        int c4 = (l & 31) * 4;
        float4 v = *reinterpret_cast<const float4*>(Wg + (size_t)(kc + kk) * 128 + c4);
        *reinterpret_cast<float4*>(dst + kk * LDA + c4) = v;
    }
}

__device__ __forceinline__ void load_w96(float* __restrict__ dst,
                                         const float* __restrict__ Wg,
                                         int kc, int col0, int tid)
{
    #pragma unroll
    for (int it = 0; it < 2; it++) {
        int l = tid + it * NTH;               // 0..1023, need < 768
        if (l < 768) {
            int kk = l / 24;
            int c4 = (l % 24) * 4;
            float4 v = *reinterpret_cast<const float4*>(
                Wg + (size_t)(kc + kk) * H_ + col0 + c4);
            *reinterpret_cast<float4*>(dst + kk * LDA + c4) = v;
        }
    }
}

// ---------------------------------------------------------------------------
// mlp128: C = relu(A @ W + b). 512 threads, 4x8 per-thread tile (f32x2),
// double-buffered weight chunks.
// ---------------------------------------------------------------------------
__device__ __forceinline__ void mlp128(const float* __restrict__ Asm,
                                       float* __restrict__ Csm,
                                       float* __restrict__ wb0,
                                       float* __restrict__ wb1,
                                       const float* __restrict__ Wg,
                                       const float* __restrict__ bg,
                                       int tid, int m0, int n0)
{
    u64 cc[4][4] = {};
    float* cur = wb0;
    float* nxt = wb1;
    load_w128(cur, Wg, 0, tid);
    __syncthreads();
    #pragma unroll 1
    for (int ch = 0; ch < 4; ch++) {
        if (ch < 3) load_w128(nxt, Wg, (ch + 1) * 32, tid);
        const int kc = ch * 32;
        #pragma unroll 8
        for (int kk = 0; kk < 32; kk++) {
            u64 ap[4];
            #pragma unroll
            for (int i = 0; i < 4; i++)
                ap[i] = pack_ff(Asm[(m0 + i) * LDA + kc + kk]);
            ulonglong2 w01 = *reinterpret_cast<const ulonglong2*>(cur + kk * LDA + n0);
            ulonglong2 w23 = *reinterpret_cast<const ulonglong2*>(cur + kk * LDA + n0 + 4);
            #pragma unroll
            for (int i = 0; i < 4; i++) {
                fma2(cc[i][0], ap[i], w01.x);
                fma2(cc[i][1], ap[i], w01.y);
                fma2(cc[i][2], ap[i], w23.x);
                fma2(cc[i][3], ap[i], w23.y);
            }
        }
        __syncthreads();
        float* t = cur; cur = nxt; nxt = t;
    }
    float bb[8];
    #pragma unroll
    for (int j = 0; j < 8; j++) bb[j] = __ldg(bg + n0 + j);
    #pragma unroll
    for (int i = 0; i < 4; i++) {
        float* cp = Csm + (m0 + i) * LDA + n0;
        #pragma unroll
        for (int jp = 0; jp < 4; jp++) {
            float2 v = unpack_ff(cc[i][jp]);
            cp[2*jp]     = fmaxf(v.x + bb[2*jp],     0.f);
            cp[2*jp + 1] = fmaxf(v.y + bb[2*jp + 1], 0.f);
        }
    }
}

// ---------------------------------------------------------------------------
// chain_kernel: fused per 128-row tile
//   emb = spikes@W_emb + b_emb ; h1 = relu(emb@W1+b1) ; s = relu(h1@W2+b2)
//   Out = s @ Wc1_sub (bc1 folded into g_pet)
// ---------------------------------------------------------------------------
__global__ __launch_bounds__(NTH, 1)
void chain_kernel(const float* __restrict__ spikes,
                  const float* __restrict__ W_emb, const float* __restrict__ b_emb,
                  const float* __restrict__ Ws1, const float* __restrict__ bs1,
                  const float* __restrict__ Ws2, const float* __restrict__ bs2,
                  const float* __restrict__ Wr1, const float* __restrict__ br1,
                  const float* __restrict__ Wr2, const float* __restrict__ br2,
                  const float* __restrict__ Wc1)
{
    extern __shared__ float sm[];
    float* actA = sm;                       // [BM][LDA]
    float* actB = sm + BM * LDA;            // [BM][LDA]
    float* wb0  = sm + 2 * BM * LDA;
    float* wb1  = wb0 + WCHUNK;

    const int chain = blockIdx.y;
    const float* W1 = chain ? Wr1 : Ws1;
    const float* b1 = chain ? br1 : bs1;
    const float* W2 = chain ? Wr2 : Ws2;
    const float* b2 = chain ? br2 : bs2;
    const float* Wc = Wc1 + (chain ? 144 * H_ : 0);
    float* Out = chain ? g_R1 : g_S1;

    const int row0 = blockIdx.x * BM;
    const int tid  = threadIdx.x;
    const int tx   = tid & 15;              // 16 col groups
    const int ty   = tid >> 4;              // 32 row groups
    const int m0   = ty * 4;
    const int n0   = tx * 8;

    // ---- Step 0: emb = spikes @ W_emb + b_emb -> actA -------------------
    // spikes^T staged at wb0[f][m] (f<16), W_emb at wb1[f][n]
    {
        {
            int l = tid;                    // 0..511
            int m = l >> 2;
            int q = l & 3;
            float4 v = *reinterpret_cast<const float4*>(
                spikes + (size_t)(row0 + m) * F_ + q * 4);
            wb0[(q * 4 + 0) * LDA + m] = v.x;
            wb0[(q * 4 + 1) * LDA + m] = v.y;
            wb0[(q * 4 + 2) * LDA + m] = v.z;
            wb0[(q * 4 + 3) * LDA + m] = v.w;

            int k  = l >> 5;
            int c4 = (l & 31) * 4;
            float4 w = *reinterpret_cast<const float4*>(W_emb + k * 128 + c4);
            *reinterpret_cast<float4*>(wb1 + k * LDA + c4) = w;
        }
        __syncthreads();

        u64 cc[4][4] = {};
        #pragma unroll
        for (int k = 0; k < 16; k++) {
            u64 ap[4];
            #pragma unroll
            for (int i = 0; i < 4; i++)
                ap[i] = pack_ff(wb0[k * LDA + m0 + i]);
            ulonglong2 w01 = *reinterpret_cast<const ulonglong2*>(wb1 + k * LDA + n0);
            ulonglong2 w23 = *reinterpret_cast<const ulonglong2*>(wb1 + k * LDA + n0 + 4);
            #pragma unroll
            for (int i = 0; i < 4; i++) {
                fma2(cc[i][0], ap[i], w01.x);
                fma2(cc[i][1], ap[i], w01.y);
                fma2(cc[i][2], ap[i], w23.x);
                fma2(cc[i][3], ap[i], w23.y);
            }
        }
        float bb[8];
        #pragma unroll
        for (int j = 0; j < 8; j++) bb[j] = __ldg(b_emb + n0 + j);
        #pragma unroll
        for (int i = 0; i < 4; i++) {
            float* cp = actA + (m0 + i) * LDA + n0;
            #pragma unroll
            for (int jp = 0; jp < 4; jp++) {
                float2 v = unpack_ff(cc[i][jp]);
                cp[2*jp]     = v.x + bb[2*jp];
                cp[2*jp + 1] = v.y + bb[2*jp + 1];
            }
        }
        __syncthreads();   // wb0/wb1 reads done before mlp128 prologue writes
    }

    // ---- Step 1: h1 = relu(emb @ W1 + b1) -> actB -----------------------
    mlp128(actA, actB, wb0, wb1, W1, b1, tid, m0, n0);
    // ---- Step 2: s = relu(h1 @ W2 + b2) -> actA -------------------------
    mlp128(actB, actA, wb0, wb1, W2, b2, tid, m0, n0);

    // ---- Step 3: Out = s @ Wc [128 x 288], 3 column chunks of 96 --------
    const int nc0 = tx * 6;
    #pragma unroll 1
    for (int c3 = 0; c3 < 3; c3++) {
        const int col0 = c3 * 96;
        u64 cc[4][3] = {};
        float* cur = wb0;
        float* nxt = wb1;
        load_w96(cur, Wc, 0, col0, tid);
        __syncthreads();
        #pragma unroll 1
        for (int ch = 0; ch < 4; ch++) {
            if (ch < 3) load_w96(nxt, Wc, (ch + 1) * 32, col0, tid);
            const int kc = ch * 32;
            #pragma unroll 8
            for (int kk = 0; kk < 32; kk++) {
                u64 ap[4];
                #pragma unroll
                for (int i = 0; i < 4; i++)
                    ap[i] = pack_ff(actA[(m0 + i) * LDA + kc + kk]);
                const float* wr = cur + kk * LDA + nc0;   // nc0 even -> 8B aligned
                u64 wp0 = *reinterpret_cast<const u64*>(wr);
                u64 wp1 = *reinterpret_cast<const u64*>(wr + 2);
                u64 wp2 = *reinterpret_cast<const u64*>(wr + 4);
                #pragma unroll
                for (int i = 0; i < 4; i++) {
                    fma2(cc[i][0], ap[i], wp0);
                    fma2(cc[i][1], ap[i], wp1);
                    fma2(cc[i][2], ap[i], wp2);
                }
            }
            __syncthreads();
            float* t = cur; cur = nxt; nxt = t;
        }
        #pragma unroll
        for (int i = 0; i < 4; i++) {
            float* op = Out + (size_t)(row0 + m0 + i) * H_ + col0 + nc0;
            #pragma unroll
            for (int jp = 0; jp < 3; jp++) {
                float2 v = unpack_ff(cc[i][jp]);
                op[2*jp]     = v.x;
                op[2*jp + 1] = v.y;
            }
        }
    }
}

// ---------------------------------------------------------------------------
// pet_kernel: pet[t][c] = pe[t+1] @ Wc1[128:144,c] + pe[t] @ Wc1[272:288,c] + bc1[c]
// ---------------------------------------------------------------------------
__global__ void pet_kernel(const float* __restrict__ Wc1,
                           const float* __restrict__ bc1)
{
    const int t = blockIdx.x;       // 0..254
    const int c = threadIdx.x;      // 0..287

    __shared__ float sv[4][8];
    if (c < 8) {
        int i = c;
        double dv = exp((double)(2 * i) * (-log(10000.0) / 16.0));
        double a1 = (double)(t + 1) * dv;
        double a0 = (double)t * dv;
        sv[0][i] = (float)sin(a1);
        sv[1][i] = (float)cos(a1);
        sv[2][i] = (float)sin(a0);
        sv[3][i] = (float)cos(a0);
    }
    __syncthreads();

    float acc = bc1[c];
    #pragma unroll
    for (int i = 0; i < 8; i++) {
        acc = fmaf(sv[0][i], Wc1[(128 + 2 * i) * H_ + c], acc);
        acc = fmaf(sv[1][i], Wc1[(129 + 2 * i) * H_ + c], acc);
        acc = fmaf(sv[2][i], Wc1[(272 + 2 * i) * H_ + c], acc);
        acc = fmaf(sv[3][i], Wc1[(273 + 2 * i) * H_ + c], acc);
    }
    g_pet[t * H_ + c] = acc;
}

// ---------------------------------------------------------------------------
// edge_kernel: per (b,t) block:
//   h[e,k] = relu(S1[b,t+1,se[e],k] + R1[b,t,re[e],k] + pet[t,k])
//   out[b,t,e,:] = h[e,:] @ Wc2 + bc2
// ---------------------------------------------------------------------------
__global__ __launch_bounds__(256)
void edge_kernel(const int* __restrict__ se, const int* __restrict__ re,
                 const float* __restrict__ Wc2, const float* __restrict__ bc2,
                 float* __restrict__ out)
{
    __shared__ float sS[128][33];
    __shared__ float sR[128][33];
    __shared__ float sW[H_ * 5];
    __shared__ float sPet[H_];

    const int t   = blockIdx.x;     // 0..254
    const int b   = blockIdx.y;     // 0..1
    const int tid = threadIdx.x;

    const float* Srow = g_S1 + (size_t)((b * T_ + t + 1) * N_) * H_;
    const float* Rrow = g_R1 + (size_t)((b * T_ + t) * N_) * H_;

    for (int l = tid; l < H_ * 5; l += 256) sW[l] = Wc2[l];
    for (int l = tid; l < H_;     l += 256) sPet[l] = g_pet[t * H_ + l];

    float bb[5];
    #pragma unroll
    for (int j = 0; j < 5; j++) bb[j] = __ldg(bc2 + j);

    int es[4], er[4];
    #pragma unroll
    for (int u = 0; u < 4; u++) {
        int e = u * 256 + tid;
        es[u] = __ldg(se + e);
        er[u] = __ldg(re + e);
    }
    float acc[4][5] = {};

    #pragma unroll 1
    for (int kc = 0; kc < H_; kc += 32) {
        __syncthreads();
        #pragma unroll
        for (int it = 0; it < 4; it++) {
            int l  = tid + it * 256;     // 0..1023
            int n  = l >> 3;
            int k4 = (l & 7) * 4;
            float4 v = *reinterpret_cast<const float4*>(Srow + (size_t)n * H_ + kc + k4);
            sS[n][k4 + 0] = v.x; sS[n][k4 + 1] = v.y;
            sS[n][k4 + 2] = v.z; sS[n][k4 + 3] = v.w;
            float4 u4 = *reinterpret_cast<const float4*>(Rrow + (size_t)n * H_ + kc + k4);
            sR[n][k4 + 0] = u4.x; sR[n][k4 + 1] = u4.y;
            sR[n][k4 + 2] = u4.z; sR[n][k4 + 3] = u4.w;
        }
        __syncthreads();
        #pragma unroll
        for (int kk = 0; kk < 32; kk++) {
            float pv = sPet[kc + kk];
            float w0 = sW[(kc + kk) * 5 + 0];
            float w1 = sW[(kc + kk) * 5 + 1];
            float w2 = sW[(kc + kk) * 5 + 2];
            float w3 = sW[(kc + kk) * 5 + 3];
            float w4 = sW[(kc + kk) * 5 + 4];
            #pragma unroll
            for (int u = 0; u < 4; u++) {
                float h = sS[es[u]][kk] + sR[er[u]][kk] + pv;
                h = fmaxf(h, 0.f);
                acc[u][0] = fmaf(h, w0, acc[u][0]);
                acc[u][1] = fmaf(h, w1, acc[u][1]);
                acc[u][2] = fmaf(h, w2, acc[u][2]);
                acc[u][3] = fmaf(h, w3, acc[u][3]);
                acc[u][4] = fmaf(h, w4, acc[u][4]);
            }
        }
    }

    #pragma unroll
    for (int u = 0; u < 4; u++) {
        int e = u * 256 + tid;
        size_t o = ((size_t)(b * 255 + t) * E_ + e) * 5;
        #pragma unroll
        for (int j = 0; j < 5; j++) out[o + j] = acc[u][j] + bb[j];
    }
}

// ---------------------------------------------------------------------------
extern "C" void kernel_launch(void* const* d_in, const int* in_sizes, int n_in,
                              void* d_out, int out_size)
{
    const float* spikes = (const float*)d_in[0];
    const float* W_emb  = (const float*)d_in[1];
    const float* b_emb  = (const float*)d_in[2];
    const float* Ws1    = (const float*)d_in[3];
    const float* bs1    = (const float*)d_in[4];
    const float* Ws2    = (const float*)d_in[5];
    const float* bs2    = (const float*)d_in[6];
    const float* Wr1    = (const float*)d_in[7];
    const float* br1    = (const float*)d_in[8];
    const float* Wr2    = (const float*)d_in[9];
    const float* br2    = (const float*)d_in[10];
    const float* Wc1    = (const float*)d_in[11];
    const float* bc1    = (const float*)d_in[12];
    const float* Wc2    = (const float*)d_in[13];
    const float* bc2    = (const float*)d_in[14];
    const int*   se     = (const int*)d_in[15];
    const int*   re     = (const int*)d_in[16];
    float* out = (float*)d_out;

    cudaFuncSetAttribute(chain_kernel,
                         cudaFuncAttributeMaxDynamicSharedMemorySize,
                         (int)CHAIN_SMEM);

    chain_kernel<<<dim3(M_TOTAL / BM, 2), NTH, CHAIN_SMEM>>>(
        spikes, W_emb, b_emb, Ws1, bs1, Ws2, bs2, Wr1, br1, Wr2, br2, Wc1);

    pet_kernel<<<255, H_>>>(Wc1, bc1);

    edge_kernel<<<dim3(255, 2), 256>>>(se, re, Wc2, bc2, out);
}

// round 9
// speedup vs baseline: 2.7244x; 2.7244x over previous
#include <cuda_runtime.h>
#include <cuda_bf16.h>
#include <cstdint>
#include <math.h>

// Problem dims
#define B_ 2
#define T_ 256
#define N_ 128
#define F_ 16
#define D_ 128
#define H_ 288
#define E_ 1024
#define M_TOTAL (B_*T_*N_)

typedef uint32_t u32;

// Scratch (allocation-free)
__device__ float g_S1[(size_t)M_TOTAL * H_];
__device__ float g_R1[(size_t)M_TOTAL * H_];
__device__ float g_pet[255 * H_];

// Fragment-ordered split-bf16 weight images.
// Layout per segment: index = ((kt*NJ + j)*32 + lane)*2 + r, r selects b0/b1.
#define OFF_EMB 0          // kt=1, NJ=16 -> 1024 u32
#define OFF_W1  1024       // kt=8, NJ=16 -> 8192
#define OFF_W2  9216       // kt=8, NJ=16 -> 8192
#define OFF_WC  17408      // 3 chunks, each kt=8, NJ=12 -> 6144
#define WF_TOTAL 35840
__device__ u32 g_Wf[2][2][WF_TOTAL];   // [chain][hi=0/lo=1][pos]

// ---------------- helpers ---------------------------------------------------
__device__ __forceinline__ u32 bpack(__nv_bfloat16 a, __nv_bfloat16 b) {
    return ((u32)__bfloat16_as_ushort(b) << 16) | (u32)__bfloat16_as_ushort(a);
}
__device__ __forceinline__ u32 split_pack(float v0, float v1, u32& lo) {
    __nv_bfloat16 h0 = __float2bfloat16(v0);
    __nv_bfloat16 h1 = __float2bfloat16(v1);
    lo = bpack(__float2bfloat16(v0 - __bfloat162float(h0)),
               __float2bfloat16(v1 - __bfloat162float(h1)));
    return bpack(h0, h1);
}
__device__ __forceinline__ void mma16816(float* d, const u32* a, u32 b0, u32 b1) {
    asm volatile(
        "mma.sync.aligned.m16n8k16.row.col.f32.bf16.bf16.f32 "
        "{%0,%1,%2,%3}, {%4,%5,%6,%7}, {%8,%9}, {%0,%1,%2,%3};"
        : "+f"(d[0]), "+f"(d[1]), "+f"(d[2]), "+f"(d[3])
        : "r"(a[0]), "r"(a[1]), "r"(a[2]), "r"(a[3]), "r"(b0), "r"(b1));
}

// ---------------------------------------------------------------------------
// prep_wf: pack weights into fragment-ordered split-bf16 images.
// B-frag (m16n8k16, col): lane(g=lane>>2, tig=lane&3), reg r:
//   elements (k, n), (k+1, n) with k = kt*16 + r*8 + 2*tig, n = 8*j + g.
// ---------------------------------------------------------------------------
__global__ void prep_wf(const float* __restrict__ W_emb,
                        const float* __restrict__ Ws1, const float* __restrict__ Ws2,
                        const float* __restrict__ Wr1, const float* __restrict__ Wr2,
                        const float* __restrict__ Wc1)
{
    const int chain = blockIdx.y;
    int pos = blockIdx.x * 256 + threadIdx.x;
    if (pos >= WF_TOTAL) return;

    const float* W; int rel, NJ, N = 128, koff = 0, coff = 0;
    if (pos < OFF_W1)      { rel = pos;          NJ = 16; W = W_emb; }
    else if (pos < OFF_W2) { rel = pos - OFF_W1; NJ = 16; W = chain ? Wr1 : Ws1; }
    else if (pos < OFF_WC) { rel = pos - OFF_W2; NJ = 16; W = chain ? Wr2 : Ws2; }
    else {
        int rel2 = pos - OFF_WC;
        int c = rel2 / 6144; rel = rel2 % 6144;
        NJ = 12; W = Wc1; N = 288; koff = chain ? 144 : 0; coff = 96 * c;
    }
    int r    = rel & 1;
    int lane = (rel >> 1) & 31;
    int t    = rel >> 6;
    int j    = t % NJ;
    int kt   = t / NJ;
    int gg   = lane >> 2;
    int tg   = lane & 3;
    int k    = kt * 16 + r * 8 + 2 * tg;
    int n    = coff + 8 * j + gg;

    float v0 = W[(size_t)(k + koff) * N + n];
    float v1 = W[(size_t)(k + 1 + koff) * N + n];
    u32 lo;
    u32 hi = split_pack(v0, v1, lo);
    g_Wf[chain][0][pos] = hi;
    g_Wf[chain][1][pos] = lo;
}

// ---------------------------------------------------------------------------
// layer128: D = A @ W (128x128), bias+relu, re-split into A frags. All regs.
// ---------------------------------------------------------------------------
__device__ __forceinline__ void layer128(float d[16][4],
                                         u32 Ah[8][4], u32 Al[8][4],
                                         const u32* __restrict__ Whi,
                                         const u32* __restrict__ Wlo,
                                         int seg, const float* __restrict__ bias,
                                         int lane, int tig)
{
    #pragma unroll
    for (int j = 0; j < 16; j++) { d[j][0]=0.f; d[j][1]=0.f; d[j][2]=0.f; d[j][3]=0.f; }
    const uint2* bhp = (const uint2*)(Whi + seg);
    const uint2* blp = (const uint2*)(Wlo + seg);
    #pragma unroll
    for (int kt = 0; kt < 8; kt++) {
        #pragma unroll
        for (int j = 0; j < 16; j++) {
            uint2 bh = __ldg(bhp + (kt * 16 + j) * 32 + lane);
            uint2 bl = __ldg(blp + (kt * 16 + j) * 32 + lane);
            mma16816(d[j], Ah[kt], bh.x, bh.y);
            mma16816(d[j], Al[kt], bh.x, bh.y);
            mma16816(d[j], Ah[kt], bl.x, bl.y);
        }
    }
    #pragma unroll
    for (int kt = 0; kt < 8; kt++) {
        float2 bA = *(const float2*)(bias + kt * 16 + 2 * tig);
        float2 bB = *(const float2*)(bias + kt * 16 + 8 + 2 * tig);
        float p0 = fmaxf(d[2*kt][0] + bA.x, 0.f), p1 = fmaxf(d[2*kt][1] + bA.y, 0.f);
        float p2 = fmaxf(d[2*kt][2] + bA.x, 0.f), p3 = fmaxf(d[2*kt][3] + bA.y, 0.f);
        float q0 = fmaxf(d[2*kt+1][0] + bB.x, 0.f), q1 = fmaxf(d[2*kt+1][1] + bB.y, 0.f);
        float q2 = fmaxf(d[2*kt+1][2] + bB.x, 0.f), q3 = fmaxf(d[2*kt+1][3] + bB.y, 0.f);
        Ah[kt][0] = split_pack(p0, p1, Al[kt][0]);
        Ah[kt][1] = split_pack(p2, p3, Al[kt][1]);
        Ah[kt][2] = split_pack(q0, q1, Al[kt][2]);
        Ah[kt][3] = split_pack(q2, q3, Al[kt][3]);
    }
}

// ---------------------------------------------------------------------------
// chain_mma: fully register-resident 4-layer chain per warp (16 rows).
// 128 threads/block = 4 warps = 64 rows; grid (1024, 2).
// ---------------------------------------------------------------------------
__global__ __launch_bounds__(128, 1)
void chain_mma(const float* __restrict__ spikes,
               const float* __restrict__ b_emb,
               const float* __restrict__ bs1, const float* __restrict__ bs2,
               const float* __restrict__ br1, const float* __restrict__ br2)
{
    const int chain = blockIdx.y;
    const int warp  = threadIdx.x >> 5;
    const int lane  = threadIdx.x & 31;
    const int g     = lane >> 2;
    const int tig   = lane & 3;
    const int r0    = blockIdx.x * 64 + warp * 16 + g;   // this lane's base row

    const u32* Whi = g_Wf[chain][0];
    const u32* Wlo = g_Wf[chain][1];
    const float* b1 = chain ? br1 : bs1;
    const float* b2 = chain ? br2 : bs2;
    float* Out = chain ? g_R1 : g_S1;

    u32 Ah[8][4], Al[8][4];
    float d[16][4];

    // ---- Layer 0: emb = spikes @ W_emb + b_emb (K=16, 1 k-tile) ----------
    {
        const float* sp = spikes + (size_t)r0 * F_;
        float2 v0 = *(const float2*)(sp + 2 * tig);
        float2 v1 = *(const float2*)(sp + 8 * F_ + 2 * tig);
        float2 v2 = *(const float2*)(sp + 2 * tig + 8);
        float2 v3 = *(const float2*)(sp + 8 * F_ + 2 * tig + 8);
        Ah[0][0] = split_pack(v0.x, v0.y, Al[0][0]);
        Ah[0][1] = split_pack(v1.x, v1.y, Al[0][1]);
        Ah[0][2] = split_pack(v2.x, v2.y, Al[0][2]);
        Ah[0][3] = split_pack(v3.x, v3.y, Al[0][3]);

        #pragma unroll
        for (int j = 0; j < 16; j++) { d[j][0]=0.f; d[j][1]=0.f; d[j][2]=0.f; d[j][3]=0.f; }
        const uint2* bhp = (const uint2*)(Whi + OFF_EMB);
        const uint2* blp = (const uint2*)(Wlo + OFF_EMB);
        #pragma unroll
        for (int j = 0; j < 16; j++) {
            uint2 bh = __ldg(bhp + j * 32 + lane);
            uint2 bl = __ldg(blp + j * 32 + lane);
            mma16816(d[j], Ah[0], bh.x, bh.y);
            mma16816(d[j], Al[0], bh.x, bh.y);
            mma16816(d[j], Ah[0], bl.x, bl.y);
        }
        // epilogue: + b_emb (no relu) -> A frags
        #pragma unroll
        for (int kt = 0; kt < 8; kt++) {
            float2 bA = *(const float2*)(b_emb + kt * 16 + 2 * tig);
            float2 bB = *(const float2*)(b_emb + kt * 16 + 8 + 2 * tig);
            float p0 = d[2*kt][0] + bA.x, p1 = d[2*kt][1] + bA.y;
            float p2 = d[2*kt][2] + bA.x, p3 = d[2*kt][3] + bA.y;
            float q0 = d[2*kt+1][0] + bB.x, q1 = d[2*kt+1][1] + bB.y;
            float q2 = d[2*kt+1][2] + bB.x, q3 = d[2*kt+1][3] + bB.y;
            Ah[kt][0] = split_pack(p0, p1, Al[kt][0]);
            Ah[kt][1] = split_pack(p2, p3, Al[kt][1]);
            Ah[kt][2] = split_pack(q0, q1, Al[kt][2]);
            Ah[kt][3] = split_pack(q2, q3, Al[kt][3]);
        }
    }

    // ---- Layers 1 & 2 ------------------------------------------------------
    layer128(d, Ah, Al, Whi, Wlo, OFF_W1, b1, lane, tig);
    layer128(d, Ah, Al, Whi, Wlo, OFF_W2, b2, lane, tig);

    // ---- Layer 3: Out = s @ Wc (N=288, 3 chunks of 96) ---------------------
    #pragma unroll 1
    for (int c = 0; c < 3; c++) {
        float d2[12][4];
        #pragma unroll
        for (int j = 0; j < 12; j++) { d2[j][0]=0.f; d2[j][1]=0.f; d2[j][2]=0.f; d2[j][3]=0.f; }
        const uint2* bhp = (const uint2*)(Whi + OFF_WC + c * 6144);
        const uint2* blp = (const uint2*)(Wlo + OFF_WC + c * 6144);
        #pragma unroll
        for (int kt = 0; kt < 8; kt++) {
            #pragma unroll
            for (int j = 0; j < 12; j++) {
                uint2 bh = __ldg(bhp + (kt * 12 + j) * 32 + lane);
                uint2 bl = __ldg(blp + (kt * 12 + j) * 32 + lane);
                mma16816(d2[j], Ah[kt], bh.x, bh.y);
                mma16816(d2[j], Al[kt], bh.x, bh.y);
                mma16816(d2[j], Ah[kt], bl.x, bl.y);
            }
        }
        #pragma unroll
        for (int j = 0; j < 12; j++) {
            int col = c * 96 + j * 8 + 2 * tig;
            *(float2*)(Out + (size_t)r0 * H_ + col)       = make_float2(d2[j][0], d2[j][1]);
            *(float2*)(Out + (size_t)(r0 + 8) * H_ + col) = make_float2(d2[j][2], d2[j][3]);
        }
    }
}

// ---------------------------------------------------------------------------
// pet_kernel (unchanged)
// ---------------------------------------------------------------------------
__global__ void pet_kernel(const float* __restrict__ Wc1,
                           const float* __restrict__ bc1)
{
    const int t = blockIdx.x;
    const int c = threadIdx.x;

    __shared__ float sv[4][8];
    if (c < 8) {
        int i = c;
        double dv = exp((double)(2 * i) * (-log(10000.0) / 16.0));
        double a1 = (double)(t + 1) * dv;
        double a0 = (double)t * dv;
        sv[0][i] = (float)sin(a1);
        sv[1][i] = (float)cos(a1);
        sv[2][i] = (float)sin(a0);
        sv[3][i] = (float)cos(a0);
    }
    __syncthreads();

    float acc = bc1[c];
    #pragma unroll
    for (int i = 0; i < 8; i++) {
        acc = fmaf(sv[0][i], Wc1[(128 + 2 * i) * H_ + c], acc);
        acc = fmaf(sv[1][i], Wc1[(129 + 2 * i) * H_ + c], acc);
        acc = fmaf(sv[2][i], Wc1[(272 + 2 * i) * H_ + c], acc);
        acc = fmaf(sv[3][i], Wc1[(273 + 2 * i) * H_ + c], acc);
    }
    g_pet[t * H_ + c] = acc;
}

// ---------------------------------------------------------------------------
// edge_kernel (unchanged from best round)
// ---------------------------------------------------------------------------
__global__ __launch_bounds__(256)
void edge_kernel(const int* __restrict__ se, const int* __restrict__ re,
                 const float* __restrict__ Wc2, const float* __restrict__ bc2,
                 float* __restrict__ out)
{
    __shared__ float sS[128][33];
    __shared__ float sR[128][33];
    __shared__ float sW[H_ * 5];
    __shared__ float sPet[H_];

    const int t   = blockIdx.x;
    const int b   = blockIdx.y;
    const int tid = threadIdx.x;

    const float* Srow = g_S1 + (size_t)((b * T_ + t + 1) * N_) * H_;
    const float* Rrow = g_R1 + (size_t)((b * T_ + t) * N_) * H_;

    for (int l = tid; l < H_ * 5; l += 256) sW[l] = Wc2[l];
    for (int l = tid; l < H_;     l += 256) sPet[l] = g_pet[t * H_ + l];

    float bb[5];
    #pragma unroll
    for (int j = 0; j < 5; j++) bb[j] = __ldg(bc2 + j);

    int es[4], er[4];
    #pragma unroll
    for (int u = 0; u < 4; u++) {
        int e = u * 256 + tid;
        es[u] = __ldg(se + e);
        er[u] = __ldg(re + e);
    }
    float acc[4][5] = {};

    #pragma unroll 1
    for (int kc = 0; kc < H_; kc += 32) {
        __syncthreads();
        #pragma unroll
        for (int it = 0; it < 4; it++) {
            int l  = tid + it * 256;
            int n  = l >> 3;
            int k4 = (l & 7) * 4;
            float4 v = *reinterpret_cast<const float4*>(Srow + (size_t)n * H_ + kc + k4);
            sS[n][k4 + 0] = v.x; sS[n][k4 + 1] = v.y;
            sS[n][k4 + 2] = v.z; sS[n][k4 + 3] = v.w;
            float4 u4 = *reinterpret_cast<const float4*>(Rrow + (size_t)n * H_ + kc + k4);
            sR[n][k4 + 0] = u4.x; sR[n][k4 + 1] = u4.y;
            sR[n][k4 + 2] = u4.z; sR[n][k4 + 3] = u4.w;
        }
        __syncthreads();
        #pragma unroll
        for (int kk = 0; kk < 32; kk++) {
            float pv = sPet[kc + kk];
            float w0 = sW[(kc + kk) * 5 + 0];
            float w1 = sW[(kc + kk) * 5 + 1];
            float w2 = sW[(kc + kk) * 5 + 2];
            float w3 = sW[(kc + kk) * 5 + 3];
            float w4 = sW[(kc + kk) * 5 + 4];
            #pragma unroll
            for (int u = 0; u < 4; u++) {
                float h = sS[es[u]][kk] + sR[er[u]][kk] + pv;
                h = fmaxf(h, 0.f);
                acc[u][0] = fmaf(h, w0, acc[u][0]);
                acc[u][1] = fmaf(h, w1, acc[u][1]);
                acc[u][2] = fmaf(h, w2, acc[u][2]);
                acc[u][3] = fmaf(h, w3, acc[u][3]);
                acc[u][4] = fmaf(h, w4, acc[u][4]);
            }
        }
    }

    #pragma unroll
    for (int u = 0; u < 4; u++) {
        int e = u * 256 + tid;
        size_t o = ((size_t)(b * 255 + t) * E_ + e) * 5;
        #pragma unroll
        for (int j = 0; j < 5; j++) out[o + j] = acc[u][j] + bb[j];
    }
}

// ---------------------------------------------------------------------------
extern "C" void kernel_launch(void* const* d_in, const int* in_sizes, int n_in,
                              void* d_out, int out_size)
{
    const float* spikes = (const float*)d_in[0];
    const float* W_emb  = (const float*)d_in[1];
    const float* b_emb  = (const float*)d_in[2];
    const float* Ws1    = (const float*)d_in[3];
    const float* bs1    = (const float*)d_in[4];
    const float* Ws2    = (const float*)d_in[5];
    const float* bs2    = (const float*)d_in[6];
    const float* Wr1    = (const float*)d_in[7];
    const float* br1    = (const float*)d_in[8];
    const float* Wr2    = (const float*)d_in[9];
    const float* br2    = (const float*)d_in[10];
    const float* Wc1    = (const float*)d_in[11];
    const float* bc1    = (const float*)d_in[12];
    const float* Wc2    = (const float*)d_in[13];
    const float* bc2    = (const float*)d_in[14];
    const int*   se     = (const int*)d_in[15];
    const int*   re     = (const int*)d_in[16];
    float* out = (float*)d_out;

    prep_wf<<<dim3((WF_TOTAL + 255) / 256, 2), 256>>>(
        W_emb, Ws1, Ws2, Wr1, Wr2, Wc1);

    chain_mma<<<dim3(M_TOTAL / 64, 2), 128>>>(
        spikes, b_emb, bs1, bs2, br1, br2);

    pet_kernel<<<255, H_>>>(Wc1, bc1);

    edge_kernel<<<dim3(255, 2), 256>>>(se, re, Wc2, bc2, out);
}